// round 1
// baseline (speedup 1.0000x reference)
#include <cuda_runtime.h>

#define B_   8
#define C_   256
#define CQ_  128
#define N_   4096

// Scratch (device globals — no allocations allowed).
__device__ float g_qkv[(size_t)B_ * 512 * N_];        //  67 MB: rows 0..127 q, 128..255 k, 256..511 v
__device__ float g_S[(size_t)B_ * N_ * N_];           // 537 MB: scores S[b][m][n]
__device__ float g_cmax[B_ * N_];
__device__ float g_crcp[B_ * N_];

// ---------------------------------------------------------------------------
// K1: fused QKV projection.  qkv[b][o][m] = W_sel[o] . x[b][:][m] + b_sel[o]
// Block tile 64(out-row) x 64(pixel), K=256 in chunks of 16.
// ---------------------------------------------------------------------------
__global__ __launch_bounds__(256) void proj_kernel(
    const float* __restrict__ x,
    const float* __restrict__ Wq, const float* __restrict__ bq,
    const float* __restrict__ Wk, const float* __restrict__ bk,
    const float* __restrict__ Wv, const float* __restrict__ bv)
{
    const int b  = blockIdx.z;
    const int i0 = blockIdx.y * 64;
    const int j0 = blockIdx.x * 64;

    const float* W; const float* bias; int ir0;
    if (i0 < CQ_)        { W = Wq; bias = bq; ir0 = i0; }
    else if (i0 < 2*CQ_) { W = Wk; bias = bk; ir0 = i0 - CQ_; }
    else                 { W = Wv; bias = bv; ir0 = i0 - 2*CQ_; }

    const float* xb = x + (size_t)b * C_ * N_;

    __shared__ float As[64][17];   // [out-row][k] (padded: near-conflict-free STS/LDS)
    __shared__ float Bs[16][64];   // [k][pixel]   (float4 reads)

    const int tx = threadIdx.x, ty = threadIdx.y;
    const int tid = ty * 16 + tx;
    float acc[4][4] = {};

    for (int kt = 0; kt < C_; kt += 16) {
        #pragma unroll
        for (int r = 0; r < 4; r++) {
            int idx = tid + r * 256;
            int kk = idx & 15, ii = idx >> 4;
            As[ii][kk] = W[(ir0 + ii) * C_ + kt + kk];
        }
        #pragma unroll
        for (int r = 0; r < 4; r++) {
            int idx = tid + r * 256;
            int jj = idx & 63, kk = idx >> 6;
            Bs[kk][jj] = xb[(size_t)(kt + kk) * N_ + j0 + jj];
        }
        __syncthreads();
        #pragma unroll
        for (int kk = 0; kk < 16; kk++) {
            float4 rb = reinterpret_cast<const float4*>(Bs[kk])[tx];
            float  ra[4];
            #pragma unroll
            for (int a = 0; a < 4; a++) ra[a] = As[ty*4 + a][kk];
            #pragma unroll
            for (int a = 0; a < 4; a++) {
                acc[a][0] += ra[a] * rb.x;
                acc[a][1] += ra[a] * rb.y;
                acc[a][2] += ra[a] * rb.z;
                acc[a][3] += ra[a] * rb.w;
            }
        }
        __syncthreads();
    }

    float* ob = g_qkv + (size_t)b * 512 * N_;
    #pragma unroll
    for (int a = 0; a < 4; a++) {
        int i = i0 + ty*4 + a;
        float bi = bias[ir0 + ty*4 + a];
        float4 o;
        o.x = acc[a][0] + bi; o.y = acc[a][1] + bi;
        o.z = acc[a][2] + bi; o.w = acc[a][3] + bi;
        reinterpret_cast<float4*>(ob + (size_t)i * N_ + j0)[tx] = o;
    }
}

// ---------------------------------------------------------------------------
// K2: scores.  S[b][m][n] = sum_c q[b][c][m] * k[b][c][n]   (K = 128)
// Both operands are K-strided with M/N contiguous -> no smem transpose needed.
// ---------------------------------------------------------------------------
__global__ __launch_bounds__(256) void scores_kernel()
{
    const int b  = blockIdx.z;
    const int m0 = blockIdx.y * 64;
    const int n0 = blockIdx.x * 64;
    const float* q = g_qkv + (size_t)b * 512 * N_;
    const float* k = q + (size_t)CQ_ * N_;

    __shared__ float Qs[16][64];
    __shared__ float Ks[16][64];

    const int tx = threadIdx.x, ty = threadIdx.y;
    const int tid = ty * 16 + tx;
    float acc[4][4] = {};

    for (int kt = 0; kt < CQ_; kt += 16) {
        #pragma unroll
        for (int r = 0; r < 4; r++) {
            int idx = tid + r * 256;
            int mm = idx & 63, kk = idx >> 6;
            Qs[kk][mm] = q[(size_t)(kt + kk) * N_ + m0 + mm];
            Ks[kk][mm] = k[(size_t)(kt + kk) * N_ + n0 + mm];
        }
        __syncthreads();
        #pragma unroll
        for (int kk = 0; kk < 16; kk++) {
            float4 ra = reinterpret_cast<const float4*>(Qs[kk])[ty];
            float4 rb = reinterpret_cast<const float4*>(Ks[kk])[tx];
            acc[0][0] += ra.x*rb.x; acc[0][1] += ra.x*rb.y; acc[0][2] += ra.x*rb.z; acc[0][3] += ra.x*rb.w;
            acc[1][0] += ra.y*rb.x; acc[1][1] += ra.y*rb.y; acc[1][2] += ra.y*rb.z; acc[1][3] += ra.y*rb.w;
            acc[2][0] += ra.z*rb.x; acc[2][1] += ra.z*rb.y; acc[2][2] += ra.z*rb.z; acc[2][3] += ra.z*rb.w;
            acc[3][0] += ra.w*rb.x; acc[3][1] += ra.w*rb.y; acc[3][2] += ra.w*rb.z; acc[3][3] += ra.w*rb.w;
        }
        __syncthreads();
    }

    float* Sb = g_S + (size_t)b * N_ * N_;
    #pragma unroll
    for (int a = 0; a < 4; a++) {
        int m = m0 + ty*4 + a;
        float4 o; o.x = acc[a][0]; o.y = acc[a][1]; o.z = acc[a][2]; o.w = acc[a][3];
        reinterpret_cast<float4*>(Sb + (size_t)m * N_ + n0)[tx] = o;
    }
}

// ---------------------------------------------------------------------------
// K3: per-column (fixed n) online max / sum(exp) over m.
// Thread t handles column n = bx*256 + t; warp reads are fully coalesced rows.
// ---------------------------------------------------------------------------
__global__ __launch_bounds__(256) void colstats_kernel()
{
    const int b = blockIdx.y;
    const int n = blockIdx.x * 256 + threadIdx.x;
    const float* Sb = g_S + (size_t)b * N_ * N_;

    float mx = -1e30f, sm = 0.f;
    for (int m = 0; m < N_; m += 8) {
        float v[8];
        #pragma unroll
        for (int u = 0; u < 8; u++) v[u] = Sb[(size_t)(m + u) * N_ + n];
        #pragma unroll
        for (int u = 0; u < 8; u++) {
            float val = v[u];
            if (val > mx) { sm = sm * __expf(mx - val) + 1.f; mx = val; }
            else          { sm += __expf(val - mx); }
        }
    }
    g_cmax[b * N_ + n] = mx;
    g_crcp[b * N_ + n] = 1.0f / sm;
}

// ---------------------------------------------------------------------------
// K4: out[b][c][m] = sum_n v[b][c][n] * P[m][n],  P = exp(S - cmax[n]) * crcp[n]
// exp applied at shared-tile load.  Epilogue: y = gamma * out + x.
// ---------------------------------------------------------------------------
__global__ __launch_bounds__(256) void out_kernel(
    const float* __restrict__ x,
    const float* __restrict__ gamma,
    float* __restrict__ y)
{
    const int b  = blockIdx.z;
    const int m0 = blockIdx.x * 64;
    const int c0 = blockIdx.y * 64;

    const float* v    = g_qkv + (size_t)b * 512 * N_ + (size_t)(2 * CQ_) * N_;
    const float* Sb   = g_S + (size_t)b * N_ * N_;
    const float* cmax = g_cmax + b * N_;
    const float* crcp = g_crcp + b * N_;

    __shared__ float Vs[64][17];   // [c][n_k]
    __shared__ float Ps[64][17];   // [m][n_k]

    const int tx = threadIdx.x, ty = threadIdx.y;
    const int tid = ty * 16 + tx;
    float acc[4][4] = {};

    for (int nt = 0; nt < N_; nt += 16) {
        #pragma unroll
        for (int r = 0; r < 4; r++) {
            int idx = tid + r * 256;
            int kk = idx & 15, ii = idx >> 4;
            Vs[ii][kk] = v[(size_t)(c0 + ii) * N_ + nt + kk];
            float s = Sb[(size_t)(m0 + ii) * N_ + nt + kk];
            Ps[ii][kk] = __expf(s - cmax[nt + kk]) * crcp[nt + kk];
        }
        __syncthreads();
        #pragma unroll
        for (int kk = 0; kk < 16; kk++) {
            float ra[4], rb[4];
            #pragma unroll
            for (int a = 0; a < 4; a++)  ra[a] = Vs[ty*4 + a][kk];
            #pragma unroll
            for (int c = 0; c < 4; c++)  rb[c] = Ps[tx*4 + c][kk];
            #pragma unroll
            for (int a = 0; a < 4; a++)
                #pragma unroll
                for (int c = 0; c < 4; c++)
                    acc[a][c] += ra[a] * rb[c];
        }
        __syncthreads();
    }

    const float g = gamma[0];
    #pragma unroll
    for (int a = 0; a < 4; a++) {
        int c = c0 + ty*4 + a;
        size_t base = ((size_t)b * C_ + c) * N_ + m0;
        float4 xi = reinterpret_cast<const float4*>(x + base)[tx];
        float4 o;
        o.x = g * acc[a][0] + xi.x;
        o.y = g * acc[a][1] + xi.y;
        o.z = g * acc[a][2] + xi.z;
        o.w = g * acc[a][3] + xi.w;
        reinterpret_cast<float4*>(y + base)[tx] = o;
    }
}

// ---------------------------------------------------------------------------
extern "C" void kernel_launch(void* const* d_in, const int* in_sizes, int n_in,
                              void* d_out, int out_size)
{
    const float* x     = (const float*)d_in[0];
    const float* Wq    = (const float*)d_in[1];
    const float* bq    = (const float*)d_in[2];
    const float* Wk    = (const float*)d_in[3];
    const float* bk    = (const float*)d_in[4];
    const float* Wv    = (const float*)d_in[5];
    const float* bv    = (const float*)d_in[6];
    const float* gamma = (const float*)d_in[7];
    float* y = (float*)d_out;

    dim3 blk(16, 16);
    proj_kernel   <<<dim3(N_/64, 512/64, B_), blk>>>(x, Wq, bq, Wk, bk, Wv, bv);
    scores_kernel <<<dim3(N_/64, N_/64, B_), blk>>>();
    colstats_kernel<<<dim3(N_/256, B_), 256>>>();
    out_kernel    <<<dim3(N_/64, C_/64, B_), blk>>>(x, gamma, y);
}

// round 3
// speedup vs baseline: 2.7484x; 2.7484x over previous
#include <cuda_runtime.h>
#include <cstdint>

#define NB 8
#define CC 256
#define CQh 128
#define NN 4096
#define RSB 80          // smem row stride bytes (20 floats) -> conflict-free frags
#define TILEB 10240     // one 128-row tile buffer (128*80)

// ---------------- scratch (device globals; no allocations allowed) ----------
__device__ float g_xT [(size_t)NB*NN*CC];      // [b][m][c]   (tf32-rounded)
__device__ float g_qk [(size_t)NB*NN*CC];      // [b][m][o] o<128:q else k
__device__ float g_v  [(size_t)NB*CC*NN];      // [b][c][m]
__device__ float g_S  [(size_t)NB*NN*NN];      // [b][m][n] fp32 scores
__device__ float g_P  [(size_t)NB*NN*NN];      // [b][m][n] tf32-rounded probs
__device__ float g_rcp[NB*NN];
__device__ float g_Wqk[2*CQh*CC];
__device__ float g_Wv [CC*CC];
__device__ float g_bias[512];                  // q:0-127 k:128-255 v:256-511

// ---------------- helpers ---------------------------------------------------
__device__ __forceinline__ uint32_t smem_u32(const void* p){
    uint32_t a;
    asm("{ .reg .u64 t; cvta.to.shared.u64 t, %1; cvt.u32.u64 %0, t; }" : "=r"(a) : "l"(p));
    return a;
}
__device__ __forceinline__ float tf32r(float x){
    uint32_t u; asm("cvt.rna.tf32.f32 %0, %1;" : "=r"(u) : "f"(x));
    return __uint_as_float(u);
}
// polynomial exp on the FMA pipe (avoids MUFU bottleneck); rel err ~1.5e-5
__device__ __forceinline__ float fexp(float x){
    float t = x * 1.44269504f;
    t = fmaxf(t, -120.f);
    float fi = floorf(t);
    float f = t - fi;
    float p = 1.54035304e-4f;
    p = fmaf(p, f, 1.33335581e-3f);
    p = fmaf(p, f, 9.61812911e-3f);
    p = fmaf(p, f, 5.55041087e-2f);
    p = fmaf(p, f, 2.40226507e-1f);
    p = fmaf(p, f, 6.93147181e-1f);
    p = fmaf(p, f, 1.0f);
    return __int_as_float(__float_as_int(p) + ((int)fi << 23));
}

// ---------------- tf32 GEMM core: D[128][128] = A(128xK) * B(128xK)^T -------
// A,B fp32 (tf32-valued) K-major, row strides lda/ldb (elements).
// 256 threads, 8 warps as 2(M) x 4(N); warp tile 64x32; mma m16n8k8.
__device__ __forceinline__ void ldchunk(uint32_t sA, uint32_t sB,
    const float* __restrict__ A, int lda, const float* __restrict__ B, int ldb,
    int kt, int buf, int tid)
{
    const float* Ak = A + kt*16;
    const float* Bk = B + kt*16;
    #pragma unroll
    for (int r = 0; r < 2; r++){
        int t = tid + r*256;
        int row = t >> 2, seg = t & 3;
        uint32_t off = (uint32_t)(buf*TILEB + row*RSB + seg*16);
        asm volatile("cp.async.ca.shared.global [%0], [%1], 16;"
            :: "r"(sA + off), "l"(Ak + (size_t)row*lda + seg*4) : "memory");
        asm volatile("cp.async.ca.shared.global [%0], [%1], 16;"
            :: "r"(sB + off), "l"(Bk + (size_t)row*ldb + seg*4) : "memory");
    }
    asm volatile("cp.async.commit_group;" ::: "memory");
}

__device__ __forceinline__ void gemm_tf32(
    const float* __restrict__ A, int lda,
    const float* __restrict__ B, int ldb,
    int K, uint8_t* smp, float acc[4][4][4])
{
    const int tid = threadIdx.x, lane = tid & 31, wid = tid >> 5;
    const int wm = wid & 1, wn = wid >> 1;
    uint32_t sA = smem_u32(smp), sB = sA + 2*TILEB;
    const int KT = K >> 4;

    ldchunk(sA, sB, A, lda, B, ldb, 0, 0, tid);
    for (int kt = 0; kt < KT; kt++){
        int buf = kt & 1;
        if (kt + 1 < KT){
            ldchunk(sA, sB, A, lda, B, ldb, kt+1, buf^1, tid);
            asm volatile("cp.async.wait_group 1;" ::: "memory");
        } else {
            asm volatile("cp.async.wait_group 0;" ::: "memory");
        }
        __syncthreads();
        uint32_t aA = sA + buf*TILEB + (wm*64 + (lane>>2))*RSB + (lane&3)*4;
        uint32_t aB = sB + buf*TILEB + (wn*32 + (lane>>2))*RSB + (lane&3)*4;
        #pragma unroll
        for (int ks = 0; ks < 2; ks++){
            uint32_t a[4][4], b[4][2];
            #pragma unroll
            for (int mi = 0; mi < 4; mi++){
                uint32_t base = aA + mi*16*RSB + ks*32;
                asm volatile("ld.shared.b32 %0, [%1];" : "=r"(a[mi][0]) : "r"(base));
                asm volatile("ld.shared.b32 %0, [%1];" : "=r"(a[mi][1]) : "r"(base + 8*RSB));
                asm volatile("ld.shared.b32 %0, [%1];" : "=r"(a[mi][2]) : "r"(base + 16));
                asm volatile("ld.shared.b32 %0, [%1];" : "=r"(a[mi][3]) : "r"(base + 8*RSB + 16));
            }
            #pragma unroll
            for (int nj = 0; nj < 4; nj++){
                uint32_t base = aB + nj*8*RSB + ks*32;
                asm volatile("ld.shared.b32 %0, [%1];" : "=r"(b[nj][0]) : "r"(base));
                asm volatile("ld.shared.b32 %0, [%1];" : "=r"(b[nj][1]) : "r"(base + 16));
            }
            #pragma unroll
            for (int mi = 0; mi < 4; mi++)
                #pragma unroll
                for (int nj = 0; nj < 4; nj++)
                    asm volatile(
                        "mma.sync.aligned.m16n8k8.row.col.f32.tf32.tf32.f32 "
                        "{%0,%1,%2,%3}, {%4,%5,%6,%7}, {%8,%9}, {%0,%1,%2,%3};"
                        : "+f"(acc[mi][nj][0]), "+f"(acc[mi][nj][1]),
                          "+f"(acc[mi][nj][2]), "+f"(acc[mi][nj][3])
                        : "r"(a[mi][0]), "r"(a[mi][1]), "r"(a[mi][2]), "r"(a[mi][3]),
                          "r"(b[nj][0]), "r"(b[nj][1]));
        }
        __syncthreads();
    }
}

#define GEMM_PROLOG                                          \
    __shared__ __align__(128) uint8_t sm[4*TILEB];           \
    const int lane = threadIdx.x & 31, wid = threadIdx.x >> 5;\
    float acc[4][4][4] = {};

// ---------------- prep kernels ----------------------------------------------
__global__ __launch_bounds__(256) void prep_w(
    const float* __restrict__ Wq, const float* __restrict__ bq,
    const float* __restrict__ Wk, const float* __restrict__ bk,
    const float* __restrict__ Wv, const float* __restrict__ bv)
{
    int i = blockIdx.x*256 + threadIdx.x;          // 65536 threads
    if (i < 32768) { g_Wqk[i] = tf32r(Wq[i]); g_Wqk[32768 + i] = tf32r(Wk[i]); }
    g_Wv[i] = tf32r(Wv[i]);
    if (i < 128) { g_bias[i] = bq[i]; g_bias[128 + i] = bk[i]; }
    if (i < 256) g_bias[256 + i] = bv[i];
}

__global__ __launch_bounds__(256) void prep_xT(const float* __restrict__ x)
{
    __shared__ float t[32][33];
    int b = blockIdx.z, m0 = blockIdx.x*32, c0 = blockIdx.y*32;
    int tx = threadIdx.x, ty = threadIdx.y;        // (32, 8)
    #pragma unroll
    for (int j = 0; j < 4; j++)
        t[ty + j*8][tx] = x[((size_t)b*CC + c0 + ty + j*8)*NN + m0 + tx];
    __syncthreads();
    #pragma unroll
    for (int j = 0; j < 4; j++)
        g_xT[((size_t)b*NN + m0 + ty + j*8)*CC + c0 + tx] = tf32r(t[tx][ty + j*8]);
}

// ---------------- GEMM kernels ----------------------------------------------
// qk[m][o] = xT[m][:].Wqk[o][:] + bias[o]
__global__ __launch_bounds__(256) void k_proj_qk()
{
    GEMM_PROLOG
    int b = blockIdx.z, m0 = blockIdx.x*128, o0 = blockIdx.y*128;
    gemm_tf32(g_xT + ((size_t)b*NN + m0)*CC, CC, g_Wqk + (size_t)o0*CC, CC, CC, sm, acc);
    int rb = m0 + (wid & 1)*64 + (lane >> 2);
    int cb = o0 + (wid >> 1)*32 + (lane & 3)*2;
    #pragma unroll
    for (int mi = 0; mi < 4; mi++)
        #pragma unroll
        for (int nj = 0; nj < 4; nj++){
            int r = rb + mi*16, c = cb + nj*8;
            float b0 = g_bias[c], b1 = g_bias[c + 1];
            float* o0p = g_qk + ((size_t)b*NN + r)*CC + c;
            *reinterpret_cast<float2*>(o0p) =
                make_float2(tf32r(acc[mi][nj][0] + b0), tf32r(acc[mi][nj][1] + b1));
            *reinterpret_cast<float2*>(o0p + 8*CC) =
                make_float2(tf32r(acc[mi][nj][2] + b0), tf32r(acc[mi][nj][3] + b1));
        }
}

// v[c][m] = Wv[c][:].xT[m][:] + bias[256+c]
__global__ __launch_bounds__(256) void k_proj_v()
{
    GEMM_PROLOG
    int b = blockIdx.z, m0 = blockIdx.x*128, c0 = blockIdx.y*128;
    gemm_tf32(g_Wv + (size_t)c0*CC, CC, g_xT + ((size_t)b*NN + m0)*CC, CC, CC, sm, acc);
    int rb = c0 + (wid & 1)*64 + (lane >> 2);
    int cb = m0 + (wid >> 1)*32 + (lane & 3)*2;
    #pragma unroll
    for (int mi = 0; mi < 4; mi++)
        #pragma unroll
        for (int nj = 0; nj < 4; nj++){
            int r = rb + mi*16, c = cb + nj*8;
            float b0 = g_bias[256 + r], b1 = g_bias[256 + r + 8];
            float* op = g_v + ((size_t)b*CC + r)*NN + c;
            *reinterpret_cast<float2*>(op) =
                make_float2(tf32r(acc[mi][nj][0] + b0), tf32r(acc[mi][nj][1] + b0));
            *reinterpret_cast<float2*>(op + 8*NN) =
                make_float2(tf32r(acc[mi][nj][2] + b1), tf32r(acc[mi][nj][3] + b1));
        }
}

// S[m][n] = q[m][:].k[n][:]
__global__ __launch_bounds__(256) void k_scores()
{
    GEMM_PROLOG
    int b = blockIdx.z, m0 = blockIdx.x*128, n0 = blockIdx.y*128;
    gemm_tf32(g_qk + ((size_t)b*NN + m0)*CC, CC,
              g_qk + ((size_t)b*NN + n0)*CC + CQh, CC, CQh, sm, acc);
    int rb = m0 + (wid & 1)*64 + (lane >> 2);
    int cb = n0 + (wid >> 1)*32 + (lane & 3)*2;
    #pragma unroll
    for (int mi = 0; mi < 4; mi++)
        #pragma unroll
        for (int nj = 0; nj < 4; nj++){
            int r = rb + mi*16, c = cb + nj*8;
            float* op = g_S + ((size_t)b*NN + r)*NN + c;
            *reinterpret_cast<float2*>(op)         = make_float2(acc[mi][nj][0], acc[mi][nj][1]);
            *reinterpret_cast<float2*>(op + 8*NN)  = make_float2(acc[mi][nj][2], acc[mi][nj][3]);
        }
}

// out[c][m] = sum_n v[c][n]*P[m][n];  y = gamma*out + x
__global__ __launch_bounds__(256) void k_out(
    const float* __restrict__ x, const float* __restrict__ gamma, float* __restrict__ y)
{
    GEMM_PROLOG
    int b = blockIdx.z, m0 = blockIdx.x*128, c0 = blockIdx.y*128;
    gemm_tf32(g_v + ((size_t)b*CC + c0)*NN, NN,
              g_P + ((size_t)b*NN + m0)*NN, NN, NN, sm, acc);
    float gm = gamma[0];
    int rb = c0 + (wid & 1)*64 + (lane >> 2);
    int cb = m0 + (wid >> 1)*32 + (lane & 3)*2;
    #pragma unroll
    for (int mi = 0; mi < 4; mi++)
        #pragma unroll
        for (int nj = 0; nj < 4; nj++){
            int r = rb + mi*16, c = cb + nj*8;
            size_t p0 = ((size_t)b*CC + r)*NN + c;
            size_t p1 = p0 + (size_t)8*NN;
            float2 x0 = *reinterpret_cast<const float2*>(x + p0);
            float2 x1 = *reinterpret_cast<const float2*>(x + p1);
            *reinterpret_cast<float2*>(y + p0) =
                make_float2(fmaf(gm, acc[mi][nj][0], x0.x), fmaf(gm, acc[mi][nj][1], x0.y));
            *reinterpret_cast<float2*>(y + p1) =
                make_float2(fmaf(gm, acc[mi][nj][2], x1.x), fmaf(gm, acc[mi][nj][3], x1.y));
        }
}

// ---------------- softmax passes --------------------------------------------
__global__ __launch_bounds__(256) void k_colsum()
{
    int b = blockIdx.y;
    int n = blockIdx.x*256 + threadIdx.x;
    const float* Sp = g_S + ((size_t)b << 24) + n;
    float a0 = 0.f, a1 = 0.f, a2 = 0.f, a3 = 0.f;
    for (int m = 0; m < NN; m += 4) {
        float s0 = Sp[(size_t)(m+0)*NN];
        float s1 = Sp[(size_t)(m+1)*NN];
        float s2 = Sp[(size_t)(m+2)*NN];
        float s3 = Sp[(size_t)(m+3)*NN];
        a0 += fexp(s0); a1 += fexp(s1); a2 += fexp(s2); a3 += fexp(s3);
    }
    g_rcp[b*NN + n] = 1.0f / (a0 + a1 + a2 + a3);
}

__global__ __launch_bounds__(256) void k_ppass()
{
    size_t rowid = blockIdx.x;                 // 0..32767
    int b = (int)(rowid >> 12);
    const float* Srow = g_S + rowid * NN;
    float* Prow = g_P + rowid * NN;
    const float4* rcp4 = reinterpret_cast<const float4*>(g_rcp + b*NN);
    for (int q = threadIdx.x; q < NN/4; q += 256) {
        float4 s = reinterpret_cast<const float4*>(Srow)[q];
        float4 rc = rcp4[q];
        float4 o;
        o.x = tf32r(fexp(s.x) * rc.x);
        o.y = tf32r(fexp(s.y) * rc.y);
        o.z = tf32r(fexp(s.z) * rc.z);
        o.w = tf32r(fexp(s.w) * rc.w);
        reinterpret_cast<float4*>(Prow)[q] = o;
    }
}

// ---------------- launcher ---------------------------------------------------
extern "C" void kernel_launch(void* const* d_in, const int* in_sizes, int n_in,
                              void* d_out, int out_size)
{
    const float* x     = (const float*)d_in[0];
    const float* Wq    = (const float*)d_in[1];
    const float* bq    = (const float*)d_in[2];
    const float* Wk    = (const float*)d_in[3];
    const float* bk    = (const float*)d_in[4];
    const float* Wv    = (const float*)d_in[5];
    const float* bv    = (const float*)d_in[6];
    const float* gamma = (const float*)d_in[7];
    float* y = (float*)d_out;

    prep_w   <<<256, 256>>>(Wq, bq, Wk, bk, Wv, bv);
    prep_xT  <<<dim3(NN/32, CC/32, NB), dim3(32, 8)>>>(x);
    k_proj_qk<<<dim3(NN/128, CC/128, NB), 256>>>();
    k_proj_v <<<dim3(NN/128, CC/128, NB), 256>>>();
    k_scores <<<dim3(NN/128, NN/128, NB), 256>>>();
    k_colsum <<<dim3(NN/256, NB), 256>>>();
    k_ppass  <<<NB*NN, 256>>>();
    k_out    <<<dim3(NN/128, CC/128, NB), 256>>>(x, gamma, y);
}

// round 5
// speedup vs baseline: 5.7206x; 2.0814x over previous
#include <cuda_runtime.h>
#include <cuda_fp16.h>
#include <cstdint>

#define NB 8
#define CC 256
#define CQh 128
#define NN 4096
#define RSB 80          // smem row stride bytes -> conflict-free fragment LDS
#define TILEB 10240     // 128 rows * 80B

// ---------------- scratch (device globals) ----------------------------------
__device__ __half g_xT [(size_t)NB*NN*CC];     // [b][m][c]
__device__ __half g_qk [(size_t)NB*NN*CC];     // [b][m][o] o<128:q else k
__device__ __half g_v  [(size_t)NB*CC*NN];     // [b][c][m]
__device__ __half g_E  [(size_t)NB*NN*NN];     // [b][m][n] = exp(S)  268MB
__device__ float  g_rcp[NB*NN];                // 1/colsum
__device__ float  g_psum[8*NB*NN];             // colsum partials (m-split 8)
__device__ __half g_Wqk[2*CQh*CC];
__device__ __half g_Wv [CC*CC];
__device__ float  g_bias[512];                 // q:0-127 k:128-255 v:256-511

// ---------------- helpers ----------------------------------------------------
__device__ __forceinline__ uint32_t smem_u32(const void* p){
    uint32_t a;
    asm("{ .reg .u64 t; cvta.to.shared.u64 t, %1; cvt.u32.u64 %0, t; }" : "=r"(a) : "l"(p));
    return a;
}
// fma-pipe exp (no MUFU bottleneck)
__device__ __forceinline__ float fexp(float x){
    float t = x * 1.44269504f;
    t = fmaxf(t, -120.f);
    float fi = floorf(t);
    float f = t - fi;
    float p = 1.54035304e-4f;
    p = fmaf(p, f, 1.33335581e-3f);
    p = fmaf(p, f, 9.61812911e-3f);
    p = fmaf(p, f, 5.55041087e-2f);
    p = fmaf(p, f, 2.40226507e-1f);
    p = fmaf(p, f, 6.93147181e-1f);
    p = fmaf(p, f, 1.0f);
    return __int_as_float(__float_as_int(p) + ((int)fi << 23));
}
// pack two floats -> f16x2 (lo, hi), saturating to finite
__device__ __forceinline__ uint32_t pack_h2_sat(float lo, float hi){
    uint32_t r;
    asm("cvt.rn.satfinite.f16x2.f32 %0, %1, %2;" : "=r"(r) : "f"(hi), "f"(lo));
    return r;
}

#define MMA_H16(acc, a, b)                                                     \
    asm volatile("mma.sync.aligned.m16n8k16.row.col.f32.f16.f16.f32 "          \
        "{%0,%1,%2,%3}, {%4,%5,%6,%7}, {%8,%9}, {%0,%1,%2,%3};"                \
        : "+f"((acc)[0]), "+f"((acc)[1]), "+f"((acc)[2]), "+f"((acc)[3])       \
        : "r"((a)[0]), "r"((a)[1]), "r"((a)[2]), "r"((a)[3]),                  \
          "r"((b)[0]), "r"((b)[1]))

// ---------------- shared fragment compute (one 32-deep K chunk) --------------
__device__ __forceinline__ void compute_chunk(uint32_t sA, uint32_t sB, int buf,
                                              int lane, int wm, int wn, float acc[4][4][4])
{
    uint32_t aA = sA + buf*TILEB + (wm*64 + (lane>>2))*RSB + (lane&3)*4;
    uint32_t aB = sB + buf*TILEB + (wn*32 + (lane>>2))*RSB + (lane&3)*4;
    #pragma unroll
    for (int ks = 0; ks < 2; ks++){
        uint32_t a[4][4], b[4][2];
        #pragma unroll
        for (int mi = 0; mi < 4; mi++){
            uint32_t base = aA + mi*16*RSB + ks*32;
            asm volatile("ld.shared.b32 %0, [%1];" : "=r"(a[mi][0]) : "r"(base));
            asm volatile("ld.shared.b32 %0, [%1];" : "=r"(a[mi][1]) : "r"(base + 8*RSB));
            asm volatile("ld.shared.b32 %0, [%1];" : "=r"(a[mi][2]) : "r"(base + 16));
            asm volatile("ld.shared.b32 %0, [%1];" : "=r"(a[mi][3]) : "r"(base + 8*RSB + 16));
        }
        #pragma unroll
        for (int nj = 0; nj < 4; nj++){
            uint32_t base = aB + nj*8*RSB + ks*32;
            asm volatile("ld.shared.b32 %0, [%1];" : "=r"(b[nj][0]) : "r"(base));
            asm volatile("ld.shared.b32 %0, [%1];" : "=r"(b[nj][1]) : "r"(base + 16));
        }
        #pragma unroll
        for (int mi = 0; mi < 4; mi++)
            #pragma unroll
            for (int nj = 0; nj < 4; nj++)
                MMA_H16(acc[mi][nj], a[mi], b[nj]);
    }
}

// ---------------- generic fp16 GEMM core (cp.async both operands) ------------
__device__ __forceinline__ void ldchunk(uint32_t sA, uint32_t sB,
    const __half* __restrict__ A, int lda, const __half* __restrict__ B, int ldb,
    int kt, int buf, int tid)
{
    const __half* Ak = A + kt*32;
    const __half* Bk = B + kt*32;
    #pragma unroll
    for (int r = 0; r < 2; r++){
        int t = tid + r*256;
        int row = t >> 2, seg = t & 3;
        uint32_t off = (uint32_t)(buf*TILEB + row*RSB + seg*16);
        asm volatile("cp.async.ca.shared.global [%0], [%1], 16;"
            :: "r"(sA + off), "l"(Ak + (size_t)row*lda + seg*8) : "memory");
        asm volatile("cp.async.ca.shared.global [%0], [%1], 16;"
            :: "r"(sB + off), "l"(Bk + (size_t)row*ldb + seg*8) : "memory");
    }
    asm volatile("cp.async.commit_group;" ::: "memory");
}

__device__ __forceinline__ void gemm_h16(
    const __half* __restrict__ A, int lda,
    const __half* __restrict__ B, int ldb,
    int K, uint8_t* smp, float acc[4][4][4])
{
    const int tid = threadIdx.x, lane = tid & 31, wid = tid >> 5;
    const int wm = wid & 1, wn = wid >> 1;
    uint32_t sA = smem_u32(smp), sB = sA + 2*TILEB;
    const int KT = K >> 5;

    ldchunk(sA, sB, A, lda, B, ldb, 0, 0, tid);
    for (int kt = 0; kt < KT; kt++){
        int buf = kt & 1;
        if (kt + 1 < KT){
            ldchunk(sA, sB, A, lda, B, ldb, kt+1, buf^1, tid);
            asm volatile("cp.async.wait_group 1;" ::: "memory");
        } else {
            asm volatile("cp.async.wait_group 0;" ::: "memory");
        }
        __syncthreads();
        compute_chunk(sA, sB, buf, lane, wm, wn, acc);
        __syncthreads();
    }
}

#define GEMM_PROLOG                                            \
    __shared__ __align__(128) uint8_t sm[4*TILEB];             \
    const int lane = threadIdx.x & 31, wid = threadIdx.x >> 5; \
    float acc[4][4][4] = {};

// ---------------- prep kernels -----------------------------------------------
__global__ __launch_bounds__(256) void prep_w(
    const float* __restrict__ Wq, const float* __restrict__ bq,
    const float* __restrict__ Wk, const float* __restrict__ bk,
    const float* __restrict__ Wv, const float* __restrict__ bv)
{
    int i = blockIdx.x*256 + threadIdx.x;          // 65536 threads
    if (i < 32768) { g_Wqk[i] = __float2half_rn(Wq[i]); g_Wqk[32768 + i] = __float2half_rn(Wk[i]); }
    g_Wv[i] = __float2half_rn(Wv[i]);
    if (i < 128) { g_bias[i] = bq[i]; g_bias[128 + i] = bk[i]; }
    if (i < 256) g_bias[256 + i] = bv[i];
}

__global__ __launch_bounds__(256) void prep_xT(const float* __restrict__ x)
{
    __shared__ float t[32][33];
    int b = blockIdx.z, m0 = blockIdx.x*32, c0 = blockIdx.y*32;
    int tx = threadIdx.x, ty = threadIdx.y;        // (32, 8)
    #pragma unroll
    for (int j = 0; j < 4; j++)
        t[ty + j*8][tx] = x[((size_t)b*CC + c0 + ty + j*8)*NN + m0 + tx];
    __syncthreads();
    #pragma unroll
    for (int j = 0; j < 4; j++)
        g_xT[((size_t)b*NN + m0 + ty + j*8)*CC + c0 + tx] = __float2half_rn(t[tx][ty + j*8]);
}

// ---------------- GEMM kernels -----------------------------------------------
// qk[m][o] = xT[m][:].Wqk[o][:] + bias[o]
__global__ __launch_bounds__(256, 2) void k_proj_qk()
{
    GEMM_PROLOG
    int b = blockIdx.z, m0 = blockIdx.x*128, o0 = blockIdx.y*128;
    gemm_h16(g_xT + ((size_t)b*NN + m0)*CC, CC, g_Wqk + (size_t)o0*CC, CC, CC, sm, acc);
    int rb = m0 + (wid & 1)*64 + (lane >> 2);
    int cb = o0 + (wid >> 1)*32 + (lane & 3)*2;
    #pragma unroll
    for (int mi = 0; mi < 4; mi++)
        #pragma unroll
        for (int nj = 0; nj < 4; nj++){
            int r = rb + mi*16, c = cb + nj*8;
            float b0 = g_bias[c], b1 = g_bias[c + 1];
            __half* op = g_qk + ((size_t)b*NN + r)*CC + c;
            *reinterpret_cast<uint32_t*>(op)        = pack_h2_sat(acc[mi][nj][0] + b0, acc[mi][nj][1] + b1);
            *reinterpret_cast<uint32_t*>(op + 8*CC) = pack_h2_sat(acc[mi][nj][2] + b0, acc[mi][nj][3] + b1);
        }
}

// v[c][m] = Wv[c][:].xT[m][:] + bias[256+c]
__global__ __launch_bounds__(256, 2) void k_proj_v()
{
    GEMM_PROLOG
    int b = blockIdx.z, m0 = blockIdx.x*128, c0 = blockIdx.y*128;
    gemm_h16(g_Wv + (size_t)c0*CC, CC, g_xT + ((size_t)b*NN + m0)*CC, CC, CC, sm, acc);
    int rb = c0 + (wid & 1)*64 + (lane >> 2);
    int cb = m0 + (wid >> 1)*32 + (lane & 3)*2;
    #pragma unroll
    for (int mi = 0; mi < 4; mi++)
        #pragma unroll
        for (int nj = 0; nj < 4; nj++){
            int r = rb + mi*16, c = cb + nj*8;
            float b0 = g_bias[256 + r], b1 = g_bias[256 + r + 8];
            __half* op = g_v + ((size_t)b*CC + r)*NN + c;
            *reinterpret_cast<uint32_t*>(op)        = pack_h2_sat(acc[mi][nj][0] + b0, acc[mi][nj][1] + b0);
            *reinterpret_cast<uint32_t*>(op + 8*NN) = pack_h2_sat(acc[mi][nj][2] + b1, acc[mi][nj][3] + b1);
        }
}

// E[m][n] = exp(q[m][:].k[n][:])   fp16 (satfinite)
__global__ __launch_bounds__(256, 2) void k_scores()
{
    GEMM_PROLOG
    int b = blockIdx.z, m0 = blockIdx.x*128, n0 = blockIdx.y*128;
    gemm_h16(g_qk + ((size_t)b*NN + m0)*CC, CC,
             g_qk + ((size_t)b*NN + n0)*CC + CQh, CC, CQh, sm, acc);
    int rb = m0 + (wid & 1)*64 + (lane >> 2);
    int cb = n0 + (wid >> 1)*32 + (lane & 3)*2;
    #pragma unroll
    for (int mi = 0; mi < 4; mi++)
        #pragma unroll
        for (int nj = 0; nj < 4; nj++){
            int r = rb + mi*16, c = cb + nj*8;
            __half* op = g_E + ((size_t)b*NN + r)*NN + c;
            *reinterpret_cast<uint32_t*>(op)        = pack_h2_sat(fexp(acc[mi][nj][0]), fexp(acc[mi][nj][1]));
            *reinterpret_cast<uint32_t*>(op + 8*NN) = pack_h2_sat(fexp(acc[mi][nj][2]), fexp(acc[mi][nj][3]));
        }
}

// ---------------- column sums (2-stage) --------------------------------------
__global__ __launch_bounds__(128) void k_colsum1()
{
    int b = blockIdx.z, ms = blockIdx.y;
    int n0 = (blockIdx.x*128 + threadIdx.x)*8;
    const uint4* p = reinterpret_cast<const uint4*>(g_E + ((size_t)b*NN + ms*512)*NN + n0);
    const size_t stride = NN/8;       // uint4 per row
    float s[8] = {};
    #pragma unroll 4
    for (int m = 0; m < 512; m++){
        uint4 v = p[(size_t)m*stride];
        const __half2* h = reinterpret_cast<const __half2*>(&v);
        #pragma unroll
        for (int j = 0; j < 4; j++){
            s[2*j]   += __low2float(h[j]);
            s[2*j+1] += __high2float(h[j]);
        }
    }
    float* ps = g_psum + (size_t)ms*NB*NN + b*NN + n0;
    #pragma unroll
    for (int j = 0; j < 8; j++) ps[j] = s[j];
}

__global__ __launch_bounds__(256) void k_colsum2()
{
    int i = blockIdx.x*256 + threadIdx.x;          // < NB*NN
    float s = 0.f;
    #pragma unroll
    for (int ms = 0; ms < 8; ms++) s += g_psum[(size_t)ms*NB*NN + i];
    g_rcp[i] = 1.0f / s;
}

// ---------------- output GEMM: fused P = E*rcp in B loader -------------------
// out[c][m] = sum_n v[c][n] * P[m][n];  y = gamma*out + x
__global__ __launch_bounds__(256, 2) void k_out(
    const float* __restrict__ x, const float* __restrict__ gamma, float* __restrict__ y)
{
    __shared__ __align__(128) uint8_t sm[4*TILEB];
    const int tid = threadIdx.x, lane = tid & 31, wid = tid >> 5;
    const int wm = wid & 1, wn = wid >> 1;
    float acc[4][4][4] = {};
    int b = blockIdx.z, m0 = blockIdx.x*128, c0 = blockIdx.y*128;
    const __half* A = g_v + ((size_t)b*CC + c0)*NN;
    const __half* E = g_E + ((size_t)b*NN + m0)*NN;
    const float* rcp = g_rcp + b*NN;
    uint32_t sA = smem_u32(sm), sB = sA + 2*TILEB;
    const int KT = NN >> 5;     // 128

    auto cpA = [&](int kt, int buf){
        const __half* Ak = A + kt*32;
        #pragma unroll
        for (int r = 0; r < 2; r++){
            int t = tid + r*256; int row = t>>2, seg = t&3;
            uint32_t off = (uint32_t)(buf*TILEB + row*RSB + seg*16);
            asm volatile("cp.async.ca.shared.global [%0], [%1], 16;"
                :: "r"(sA + off), "l"(Ak + (size_t)row*NN + seg*8) : "memory");
        }
        asm volatile("cp.async.commit_group;" ::: "memory");
    };
    auto ldB = [&](int kt, uint4* v){
        const __half* Ek = E + kt*32;
        #pragma unroll
        for (int r = 0; r < 2; r++){
            int t = tid + r*256; int row = t>>2, seg = t&3;
            v[r] = *reinterpret_cast<const uint4*>(Ek + (size_t)row*NN + seg*8);
        }
    };
    auto stB = [&](int kt, int buf, uint4* v){
        #pragma unroll
        for (int r = 0; r < 2; r++){
            int t = tid + r*256; int row = t>>2, seg = t&3;
            int nb = kt*32 + seg*8;
            float4 c0f = *reinterpret_cast<const float4*>(rcp + nb);
            float4 c1f = *reinterpret_cast<const float4*>(rcp + nb + 4);
            const __half2* h = reinterpret_cast<const __half2*>(&v[r]);
            uint4 o;
            o.x = pack_h2_sat(__low2float(h[0])*c0f.x, __high2float(h[0])*c0f.y);
            o.y = pack_h2_sat(__low2float(h[1])*c0f.z, __high2float(h[1])*c0f.w);
            o.z = pack_h2_sat(__low2float(h[2])*c1f.x, __high2float(h[2])*c1f.y);
            o.w = pack_h2_sat(__low2float(h[3])*c1f.z, __high2float(h[3])*c1f.w);
            *reinterpret_cast<uint4*>(sm + 2*TILEB + buf*TILEB + row*RSB + seg*16) = o;
        }
    };

    // prologue: chunk 0
    {
        uint4 v[2];
        cpA(0, 0);
        ldB(0, v);
        stB(0, 0, v);
        asm volatile("cp.async.wait_group 0;" ::: "memory");
        __syncthreads();
    }
    for (int kt = 0; kt < KT; kt++){
        int buf = kt & 1;
        uint4 v[2];
        if (kt + 1 < KT){
            cpA(kt+1, buf^1);
            ldB(kt+1, v);
        }
        compute_chunk(sA, sB, buf, lane, wm, wn, acc);
        if (kt + 1 < KT){
            stB(kt+1, buf^1, v);
            asm volatile("cp.async.wait_group 0;" ::: "memory");
        }
        __syncthreads();
    }

    float gm = gamma[0];
    int rb = c0 + wm*64 + (lane >> 2);
    int cb = m0 + wn*32 + (lane & 3)*2;
    #pragma unroll
    for (int mi = 0; mi < 4; mi++)
        #pragma unroll
        for (int nj = 0; nj < 4; nj++){
            int r = rb + mi*16, c = cb + nj*8;
            size_t p0 = ((size_t)b*CC + r)*NN + c;
            size_t p1 = p0 + (size_t)8*NN;
            float2 x0 = *reinterpret_cast<const float2*>(x + p0);
            float2 x1 = *reinterpret_cast<const float2*>(x + p1);
            *reinterpret_cast<float2*>(y + p0) =
                make_float2(fmaf(gm, acc[mi][nj][0], x0.x), fmaf(gm, acc[mi][nj][1], x0.y));
            *reinterpret_cast<float2*>(y + p1) =
                make_float2(fmaf(gm, acc[mi][nj][2], x1.x), fmaf(gm, acc[mi][nj][3], x1.y));
        }
}

// ---------------- launcher ---------------------------------------------------
extern "C" void kernel_launch(void* const* d_in, const int* in_sizes, int n_in,
                              void* d_out, int out_size)
{
    const float* x     = (const float*)d_in[0];
    const float* Wq    = (const float*)d_in[1];
    const float* bq    = (const float*)d_in[2];
    const float* Wk    = (const float*)d_in[3];
    const float* bk    = (const float*)d_in[4];
    const float* Wv    = (const float*)d_in[5];
    const float* bv    = (const float*)d_in[6];
    const float* gamma = (const float*)d_in[7];
    float* y = (float*)d_out;

    prep_w   <<<256, 256>>>(Wq, bq, Wk, bk, Wv, bv);
    prep_xT  <<<dim3(NN/32, CC/32, NB), dim3(32, 8)>>>(x);
    k_proj_qk<<<dim3(NN/128, CC/128, NB), 256>>>();
    k_proj_v <<<dim3(NN/128, CC/128, NB), 256>>>();
    k_scores <<<dim3(NN/128, NN/128, NB), 256>>>();
    k_colsum1<<<dim3(NN/8/128, 8, NB), 128>>>();
    k_colsum2<<<NB*NN/256, 256>>>();
    k_out    <<<dim3(NN/128, CC/128, NB), 256>>>(x, gamma, y);
}